// round 4
// baseline (speedup 1.0000x reference)
#include <cuda_runtime.h>

// out[t, e] = W[e, idx[t]] + b[e]
// X: int32 [65536], W: f32 [128, 500000], b: f32 [128], out: f32 [65536, 128]
//
// Counting-sort tokens into 4096 index bins (bin = idx >> 7, 128 cols/bin) so
// the gather walks W in near-sorted order. Rank captured during histogram so
// scatter needs no atomics.

#define EMBED       128
#define NUM_LABELS  500000LL
#define TOK_PER_BLK 16
#define NT          65536
#define NBINS       4096
#define BIN_SHIFT   7      // 499999 >> 7 = 3906 < 4096
#define HIST_ILP    4

__device__ int g_hist[NBINS];
__device__ int g_base[NBINS];
__device__ int g_rank[NT];
__device__ int g_perm[NT];

__global__ void k_zero_hist()
{
    g_hist[blockIdx.x * blockDim.x + threadIdx.x] = 0;
}

// histogram + rank capture (one atomic pass total)
__global__ void k_hist(const int* __restrict__ X, int n)
{
    int t0 = (blockIdx.x * blockDim.x + threadIdx.x) * HIST_ILP;
    int idx[HIST_ILP];
#pragma unroll
    for (int j = 0; j < HIST_ILP; j++)
        idx[j] = (t0 + j < n) ? X[t0 + j] : -1;
#pragma unroll
    for (int j = 0; j < HIST_ILP; j++) {
        if (idx[j] >= 0)
            g_rank[t0 + j] = atomicAdd(&g_hist[idx[j] >> BIN_SHIFT], 1);
    }
}

// 1 block, 1024 threads, 4 bins each: exclusive prefix sum -> g_base
__global__ void k_scan()
{
    __shared__ int s[1024];
    int i = threadIdx.x;

    int v[4];
#pragma unroll
    for (int j = 0; j < 4; j++)
        v[j] = g_hist[i * 4 + j];
    int sum = v[0] + v[1] + v[2] + v[3];

    s[i] = sum;
    __syncthreads();
    for (int off = 1; off < 1024; off <<= 1) {
        int x = (i >= off) ? s[i - off] : 0;
        __syncthreads();
        s[i] += x;
        __syncthreads();
    }
    int base = s[i] - sum;   // exclusive across thread groups
#pragma unroll
    for (int j = 0; j < 4; j++) {
        g_base[i * 4 + j] = base;
        base += v[j];
    }
}

// atomic-free scatter
__global__ void k_scatter(const int* __restrict__ X, int n)
{
    int t0 = (blockIdx.x * blockDim.x + threadIdx.x) * HIST_ILP;
#pragma unroll
    for (int j = 0; j < HIST_ILP; j++) {
        int t = t0 + j;
        if (t < n) {
            int bin = X[t] >> BIN_SHIFT;
            g_perm[g_base[bin] + g_rank[t]] = t;
        }
    }
}

__global__ __launch_bounds__(EMBED) void k_gather(
    const int* __restrict__ X,
    const float* __restrict__ W,
    const float* __restrict__ b,
    float* __restrict__ out)
{
    const int e = threadIdx.x;                       // embed row, 0..127
    const long long row_base = (long long)e * NUM_LABELS;
    const float bias = __ldg(b + e);

    const int t0 = blockIdx.x * TOK_PER_BLK;

    int tok[TOK_PER_BLK];
#pragma unroll
    for (int j = 0; j < TOK_PER_BLK; j++)
        tok[j] = g_perm[t0 + j];

    int idx[TOK_PER_BLK];
#pragma unroll
    for (int j = 0; j < TOK_PER_BLK; j++)
        idx[j] = __ldg(X + tok[j]);

    float v[TOK_PER_BLK];
#pragma unroll
    for (int j = 0; j < TOK_PER_BLK; j++)
        v[j] = __ldg(W + row_base + (long long)idx[j]);

#pragma unroll
    for (int j = 0; j < TOK_PER_BLK; j++)
        out[(long long)tok[j] * EMBED + e] = v[j] + bias;
}

extern "C" void kernel_launch(void* const* d_in, const int* in_sizes, int n_in,
                              void* d_out, int out_size)
{
    const int*   X = (const int*)d_in[0];      // [B, S, 1] int32
    const float* W = (const float*)d_in[1];    // [128, 500000] f32
    const float* b = (const float*)d_in[2];    // [128] f32
    float*     out = (float*)d_out;            // [B, S, 128] f32

    const int n_tokens = in_sizes[0];          // 65536
    const int hs_blocks = (n_tokens + 256 * HIST_ILP - 1) / (256 * HIST_ILP);

    k_zero_hist<<<NBINS / 256, 256>>>();
    k_hist<<<hs_blocks, 256>>>(X, n_tokens);
    k_scan<<<1, 1024>>>();
    k_scatter<<<hs_blocks, 256>>>(X, n_tokens);
    k_gather<<<n_tokens / TOK_PER_BLK, EMBED>>>(X, W, b, out);
}